// round 6
// baseline (speedup 1.0000x reference)
#include <cuda_runtime.h>
#include <cstdint>

// Problem constants (fixed by setup_inputs)
#define B_   16
#define A_   16
#define T_   14
#define S_   1024
#define S2_  512       // estimated (even) subcarriers
#define SYM0 2
#define SYM1 11
#define NUNITS (B_ * S2_)   // 8192 (b, s2) units

// Output (verified R3/R5): real part only, float32, shape (B, R=1, T, S, A, A).
//   cov[b, s, i, j] = 0.5 * sum_{sym in {2,11}} Re( y[b,i,sym,2*(s>>1)] * conj(y[b,j,sym,2*(s>>1)]) )
// broadcast over t (14 copies), s and s+1 share the tile (closest even sc).
//
// R6 design: ONE WAVE, WARP PER UNIT.
//   grid = 296 blocks x 1024 threads = 9472 warps = 148 SMs x 64 warps,
//   exactly 2 blocks/SM -> zero wave quantization (R5 lost ~13.5% to a
//   46%-occupied 4th wave). Warp w owns unit (b, s2) = (w>>9, w&511):
//   gather 32 complex pilots into a private smem slab (syncwarp only),
//   each lane computes 2 float4 of the 16x16 real cov tile, then streams
//   14 t-copies; per t the warp writes 2KB fully contiguous (both
//   subcarrier tiles) with evict-first stores.
__global__ __launch_bounds__(1024, 2)
void cov_warp_kernel(const float* __restrict__ y_real,
                     const float* __restrict__ y_imag,
                     float4*      __restrict__ out4,
                     size_t n4)                     // float4 capacity (fault guard)
{
    __shared__ float2 sv[32][2][A_];   // per-warp slab: [warp][pilot][antenna]

    const int tid  = threadIdx.x;
    const int wl   = tid >> 5;                         // warp within block
    const int lane = tid & 31;
    const int w    = blockIdx.x * 32 + wl;             // global warp id = unit id
    if (w >= NUNITS) return;

    const int b  = w >> 9;
    const int s2 = w & (S2_ - 1);

    // ---- gather: 32 lanes = 2 sym x 16 ant complex ----
    {
        const int k   = lane >> 4;
        const int a   = lane & (A_ - 1);
        const int sym = k ? SYM1 : SYM0;
        const long off = (((long)(b * A_ + a)) * T_ + sym) * S_ + 2 * s2;
        sv[wl][k][a] = make_float2(__ldg(y_real + off), __ldg(y_imag + off));
    }
    __syncwarp();

    // ---- compute 2 float4 per lane: q = lane (i=lane>>2), q = lane+32 (i=8+lane>>2) ----
    const int j0 = (lane & 3) << 2;
    const int ia = lane >> 2;
    const int ib = 8 + ia;

    const float2 via0 = sv[wl][0][ia], via1 = sv[wl][1][ia];
    const float2 vib0 = sv[wl][0][ib], vib1 = sv[wl][1][ib];

    float4 va, vb;
#pragma unroll
    for (int d = 0; d < 4; ++d) {
        const float2 u = sv[wl][0][j0 + d];
        const float2 x = sv[wl][1][j0 + d];
        const float ra = 0.5f * (via0.x * u.x + via0.y * u.y + via1.x * x.x + via1.y * x.y);
        const float rb = 0.5f * (vib0.x * u.x + vib0.y * u.y + vib1.x * x.x + vib1.y * x.y);
        (&va.x)[d] = ra;
        (&vb.x)[d] = rb;
    }

    // ---- broadcast: 14 t-copies, each = 2KB contiguous per warp ----
    // out float4 index: ((b*T + t)*S + s)*64 + q ; s in {2*s2, 2*s2+1} contiguous.
    size_t base = ((size_t)(b * T_) * S_ + 2 * (size_t)s2) * 64 + lane;
    const size_t t_stride = (size_t)S_ * 64;

    // Uniform guard: largest index this warp will touch.
    const bool ok = (base + (size_t)(T_ - 1) * t_stride + 96) < n4;

    if (ok) {
#pragma unroll
        for (int t = 0; t < T_; ++t) {
            __stcs(out4 + base,      va);   // s = 2*s2,   q = lane
            __stcs(out4 + base + 32, vb);   // s = 2*s2,   q = lane+32
            __stcs(out4 + base + 64, va);   // s = 2*s2+1, q = lane
            __stcs(out4 + base + 96, vb);   // s = 2*s2+1, q = lane+32
            base += t_stride;
        }
    }
}

extern "C" void kernel_launch(void* const* d_in, const int* in_sizes, int n_in,
                              void* d_out, int out_size)
{
    // Identify the two big float arrays (3,670,016 elements each) by size;
    // disambiguate real/imag by input ordering (verified in R3).
    const float* big[2] = {nullptr, nullptr};
    int nbig = 0;
    for (int i = 0; i < n_in; ++i) {
        if (in_sizes[i] > 100000 && nbig < 2) big[nbig++] = (const float*)d_in[i];
    }

    const float* y_real;
    const float* y_imag;
    if (in_sizes[0] > 100000) {
        y_real = big[0]; y_imag = big[1];   // insertion order (verified)
    } else {
        y_imag = big[0]; y_real = big[1];   // alphabetical order
    }

    cov_warp_kernel<<<296, 1024>>>(y_real, y_imag,
                                   (float4*)d_out, (size_t)out_size / 4);
}

// round 7
// speedup vs baseline: 1.1015x; 1.1015x over previous
#include <cuda_runtime.h>
#include <cstdint>

// Problem constants (fixed by setup_inputs)
#define B_   16
#define A_   16
#define T_   14
#define S_   1024
#define S2_  512       // estimated (even) subcarriers
#define SYM0 2
#define SYM1 11

// Persist region: first 6*2^20 float4 = ~100.7 MB of the output kept in L2
// with evict_last. Across graph replays these lines are rewritten IN PLACE in
// L2 and never drain, cutting steady-state DRAM write traffic 235 -> ~134 MB.
#define PERSIST_N4 (6u * 1024u * 1024u)

__device__ __forceinline__ void store_policy(float4* __restrict__ out4,
                                             size_t idx, size_t n4,
                                             unsigned long long pol, float4 v)
{
    if (idx >= n4) return;
    float4* p = out4 + idx;
    if (idx < (size_t)PERSIST_N4) {
        asm volatile("st.global.L2::cache_hint.v4.f32 [%0], {%1,%2,%3,%4}, %5;"
                     :: "l"(p), "f"(v.x), "f"(v.y), "f"(v.z), "f"(v.w), "l"(pol)
                     : "memory");
    } else {
        __stcs(p, v);            // evict-first streaming store
    }
}

// Output (verified R3/R5): real part only, float32, shape (B, R=1, T, S, A, A).
//   cov[b, s, i, j] = 0.5 * sum_{sym in {2,11}} Re( y[b,i,sym,2*(s>>1)] * conj(y[b,j,sym,2*(s>>1)]) )
// broadcast over t (14 copies); s and s+1 share the tile (closest even sc).
//
// R7 = R5 structure (best known: compute once, broadcast-store, 4096 blocks
// x 256 threads, 4KB contiguous burst per block per t) + L2-persist policy
// on the low ~100 MB of the output.
__global__ __launch_bounds__(256, 8)
void cov_bcast2_kernel(const float* __restrict__ y_real,
                       const float* __restrict__ y_imag,
                       float4*      __restrict__ out4,
                       size_t n4)                      // float4 capacity (fault guard)
{
    __shared__ float2 sv[2][2][A_];   // [s2_local][pilot][antenna]

    const int bid = blockIdx.x;
    const int b   = bid >> 8;                  // / 256 pairs
    const int p   = bid & 255;                 // s2 pair index: s2 = 2p, 2p+1
    const int tid = threadIdx.x;

    // ---- gather: threads 0..63 load 2 s2 x 2 sym x 16 ant complex ----
    if (tid < 64) {
        const int a   = tid & (A_ - 1);
        const int k   = (tid >> 4) & 1;
        const int c   = tid >> 5;              // s2_local 0/1
        const int sym = k ? SYM1 : SYM0;
        const int sc  = 4 * p + 2 * c;         // even subcarrier 2*(2p+c)
        const long off = (((long)(b * A_ + a)) * T_ + sym) * S_ + sc;
        sv[c][k][a] = make_float2(__ldg(y_real + off), __ldg(y_imag + off));
    }
    __syncthreads();

    // ---- compute ONE float4 (4 adjacent j of real cov) per thread ----
    const int q        = tid & 63;             // float4 within one A*A tile
    const int sc_local = tid >> 6;             // 0..3 -> output sc = 4p + sc_local
    const int c        = sc_local >> 1;        // source s2_local
    const int i        = q >> 2;
    const int j0       = (q & 3) << 2;

    const float2 vi0 = sv[c][0][i];
    const float2 vi1 = sv[c][1][i];

    float4 val;
    {
        float2 u = sv[c][0][j0 + 0], w = sv[c][1][j0 + 0];
        val.x = 0.5f * (vi0.x * u.x + vi0.y * u.y + vi1.x * w.x + vi1.y * w.y);
        u = sv[c][0][j0 + 1]; w = sv[c][1][j0 + 1];
        val.y = 0.5f * (vi0.x * u.x + vi0.y * u.y + vi1.x * w.x + vi1.y * w.y);
        u = sv[c][0][j0 + 2]; w = sv[c][1][j0 + 2];
        val.z = 0.5f * (vi0.x * u.x + vi0.y * u.y + vi1.x * w.x + vi1.y * w.y);
        u = sv[c][0][j0 + 3]; w = sv[c][1][j0 + 3];
        val.w = 0.5f * (vi0.x * u.x + vi0.y * u.y + vi1.x * w.x + vi1.y * w.y);
    }

    // L2 evict_last policy (created once per thread; cheap).
    unsigned long long pol;
    asm("createpolicy.fractional.L2::evict_last.b64 %0, 1.0;" : "=l"(pol));

    // ---- broadcast: 14 stores, 4KB contiguous per block per t ----
    // out float4 index: ((b*T + t)*S + 4p + sc_local) * 64 + q
    size_t idx = ((size_t)(b * T_) * S_ + 4 * (size_t)p + sc_local) * 64 + q;
    const size_t t_stride = (size_t)S_ * 64;

#pragma unroll
    for (int t = 0; t < T_; ++t) {
        store_policy(out4, idx, n4, pol, val);
        idx += t_stride;
    }
}

extern "C" void kernel_launch(void* const* d_in, const int* in_sizes, int n_in,
                              void* d_out, int out_size)
{
    // Identify the two big float arrays (3,670,016 elements each) by size;
    // disambiguate real/imag by input ordering (verified in R3).
    const float* big[2] = {nullptr, nullptr};
    int nbig = 0;
    for (int i = 0; i < n_in; ++i) {
        if (in_sizes[i] > 100000 && nbig < 2) big[nbig++] = (const float*)d_in[i];
    }

    const float* y_real;
    const float* y_imag;
    if (in_sizes[0] > 100000) {
        y_real = big[0]; y_imag = big[1];   // insertion order (verified)
    } else {
        y_imag = big[0]; y_real = big[1];   // alphabetical order
    }

    cov_bcast2_kernel<<<B_ * (S2_ / 2), 256>>>(y_real, y_imag,
                                               (float4*)d_out,
                                               (size_t)out_size / 4);
}

// round 8
// speedup vs baseline: 1.1604x; 1.0535x over previous
#include <cuda_runtime.h>
#include <cstdint>

// Problem constants (fixed by setup_inputs)
#define B_   16
#define A_   16
#define T_   14
#define S_   1024
#define S2_  512       // estimated (even) subcarriers
#define SYM0 2
#define SYM1 11

// Persist set: all output for b < 4 (first 58.7 MB, ~29 MB per L2 die).
// Written with evict_last so the lines survive the remaining ~176 MB of
// evict-first streaming traffic and are rewritten IN PLACE in L2 on the next
// graph replay -> steady-state DRAM write traffic drops 235 -> ~176 MB.
// Policy is uniform per block: zero inner-loop overhead vs R5.
#define PERSIST_B 4

// Output (verified R3/R5): real part only, float32, shape (B, R=1, T, S, A, A).
//   cov[b, s, i, j] = 0.5 * sum_{sym in {2,11}} Re( y[b,i,sym,2*(s>>1)] * conj(y[b,j,sym,2*(s>>1)]) )
// broadcast over t (14 copies); s and s+1 share the tile (closest even sc).
//
// Structure = R5 (best known: 4096 blocks x 256 threads, compute once,
// 14 broadcast stores, 4KB contiguous burst per block per t).
__global__ __launch_bounds__(256, 8)
void cov_bcast2_kernel(const float* __restrict__ y_real,
                       const float* __restrict__ y_imag,
                       float4*      __restrict__ out4,
                       size_t n4)                      // float4 capacity (fault guard)
{
    __shared__ float2 sv[2][2][A_];   // [s2_local][pilot][antenna]

    const int bid = blockIdx.x;
    const int b   = bid >> 8;                  // / 256 pairs
    const int p   = bid & 255;                 // s2 pair index: s2 = 2p, 2p+1
    const int tid = threadIdx.x;

    // ---- gather: threads 0..63 load 2 s2 x 2 sym x 16 ant complex ----
    if (tid < 64) {
        const int a   = tid & (A_ - 1);
        const int k   = (tid >> 4) & 1;
        const int c   = tid >> 5;              // s2_local 0/1
        const int sym = k ? SYM1 : SYM0;
        const int sc  = 4 * p + 2 * c;         // even subcarrier 2*(2p+c)
        const long off = (((long)(b * A_ + a)) * T_ + sym) * S_ + sc;
        sv[c][k][a] = make_float2(__ldg(y_real + off), __ldg(y_imag + off));
    }
    __syncthreads();

    // ---- compute ONE float4 (4 adjacent j of real cov) per thread ----
    const int q        = tid & 63;             // float4 within one A*A tile
    const int sc_local = tid >> 6;             // 0..3 -> output sc = 4p + sc_local
    const int c        = sc_local >> 1;        // source s2_local
    const int i        = q >> 2;
    const int j0       = (q & 3) << 2;

    const float2 vi0 = sv[c][0][i];
    const float2 vi1 = sv[c][1][i];

    float4 val;
    {
        float2 u = sv[c][0][j0 + 0], w = sv[c][1][j0 + 0];
        val.x = 0.5f * (vi0.x * u.x + vi0.y * u.y + vi1.x * w.x + vi1.y * w.y);
        u = sv[c][0][j0 + 1]; w = sv[c][1][j0 + 1];
        val.y = 0.5f * (vi0.x * u.x + vi0.y * u.y + vi1.x * w.x + vi1.y * w.y);
        u = sv[c][0][j0 + 2]; w = sv[c][1][j0 + 2];
        val.z = 0.5f * (vi0.x * u.x + vi0.y * u.y + vi1.x * w.x + vi1.y * w.y);
        u = sv[c][0][j0 + 3]; w = sv[c][1][j0 + 3];
        val.w = 0.5f * (vi0.x * u.x + vi0.y * u.y + vi1.x * w.x + vi1.y * w.y);
    }

    // ---- broadcast: 14 stores, 4KB contiguous per block per t ----
    // out float4 index: ((b*T + t)*S + 4p + sc_local) * 64 + q
    size_t idx = ((size_t)(b * T_) * S_ + 4 * (size_t)p + sc_local) * 64 + q;
    const size_t t_stride = (size_t)S_ * 64;

    if (b < PERSIST_B) {
        // Persist path: evict_last so these lines stay L2-resident across
        // graph replays and are rewritten in place.
        unsigned long long pol;
        asm("createpolicy.fractional.L2::evict_last.b64 %0, 1.0;" : "=l"(pol));
#pragma unroll
        for (int t = 0; t < T_; ++t) {
            if (idx < n4) {
                asm volatile("st.global.L2::cache_hint.v4.f32 [%0], {%1,%2,%3,%4}, %5;"
                             :: "l"(out4 + idx),
                                "f"(val.x), "f"(val.y), "f"(val.z), "f"(val.w),
                                "l"(pol)
                             : "memory");
            }
            idx += t_stride;
        }
    } else {
        // Streaming path: evict-first, identical to R5.
#pragma unroll
        for (int t = 0; t < T_; ++t) {
            if (idx < n4) __stcs(out4 + idx, val);
            idx += t_stride;
        }
    }
}

extern "C" void kernel_launch(void* const* d_in, const int* in_sizes, int n_in,
                              void* d_out, int out_size)
{
    // Identify the two big float arrays (3,670,016 elements each) by size;
    // disambiguate real/imag by input ordering (verified in R3).
    const float* big[2] = {nullptr, nullptr};
    int nbig = 0;
    for (int i = 0; i < n_in; ++i) {
        if (in_sizes[i] > 100000 && nbig < 2) big[nbig++] = (const float*)d_in[i];
    }

    const float* y_real;
    const float* y_imag;
    if (in_sizes[0] > 100000) {
        y_real = big[0]; y_imag = big[1];   // insertion order (verified)
    } else {
        y_imag = big[0]; y_real = big[1];   // alphabetical order
    }

    cov_bcast2_kernel<<<B_ * (S2_ / 2), 256>>>(y_real, y_imag,
                                               (float4*)d_out,
                                               (size_t)out_size / 4);
}

// round 9
// speedup vs baseline: 1.2132x; 1.0456x over previous
#include <cuda_runtime.h>
#include <cstdint>

// Problem constants (fixed by setup_inputs)
#define B_   16
#define A_   16
#define T_   14
#define S_   1024
#define S2_  512       // estimated (even) subcarriers
#define SYM0 2
#define SYM1 11

// Expected output: real part only, float32, shape (B, R=1, T, S, A, A)
//   = 58,720,256 floats = 14,680,064 float4 (verified in R3).
#define FULL_N4 14680064u

// cov[b, s, i, j] = 0.5 * sum_{sym in {2,11}} Re( y[b,i,sym,2*(s>>1)] * conj(y[b,j,sym,2*(s>>1)]) )
// broadcast over t (14 copies); s and s+1 share the tile (closest even sc).
//
// R9 = R5 (best known: 4096 blocks x 256 threads, compute once, 14
// broadcast stores, 4KB contiguous burst per block per t) with the
// per-store bounds check compiled out when out_size matches (GUARDED=false),
// leaving a pure unrolled STG.128 stream.
template <bool GUARDED>
__global__ __launch_bounds__(256, 8)
void cov_bcast2_kernel(const float* __restrict__ y_real,
                       const float* __restrict__ y_imag,
                       float4*      __restrict__ out4,
                       size_t n4)
{
    __shared__ float2 sv[2][2][A_];   // [s2_local][pilot][antenna]

    const int bid = blockIdx.x;
    const int b   = bid >> 8;                  // batch
    const int p   = bid & 255;                 // s2 pair index: s2 = 2p, 2p+1
    const int tid = threadIdx.x;

    // ---- gather: threads 0..63 load 2 s2 x 2 sym x 16 ant complex ----
    if (tid < 64) {
        const int a   = tid & (A_ - 1);
        const int k   = (tid >> 4) & 1;
        const int c   = tid >> 5;              // s2_local 0/1
        const int sym = k ? SYM1 : SYM0;
        const int sc  = 4 * p + 2 * c;         // even subcarrier 2*(2p+c)
        const long off = (((long)(b * A_ + a)) * T_ + sym) * S_ + sc;
        sv[c][k][a] = make_float2(__ldg(y_real + off), __ldg(y_imag + off));
    }
    __syncthreads();

    // ---- compute ONE float4 (4 adjacent j of real cov) per thread ----
    const int q        = tid & 63;             // float4 within one A*A tile
    const int sc_local = tid >> 6;             // 0..3 -> output sc = 4p + sc_local
    const int c        = sc_local >> 1;        // source s2_local
    const int i        = q >> 2;
    const int j0       = (q & 3) << 2;

    const float2 vi0 = sv[c][0][i];
    const float2 vi1 = sv[c][1][i];

    float4 val;
    {
        float2 u = sv[c][0][j0 + 0], w = sv[c][1][j0 + 0];
        val.x = 0.5f * (vi0.x * u.x + vi0.y * u.y + vi1.x * w.x + vi1.y * w.y);
        u = sv[c][0][j0 + 1]; w = sv[c][1][j0 + 1];
        val.y = 0.5f * (vi0.x * u.x + vi0.y * u.y + vi1.x * w.x + vi1.y * w.y);
        u = sv[c][0][j0 + 2]; w = sv[c][1][j0 + 2];
        val.z = 0.5f * (vi0.x * u.x + vi0.y * u.y + vi1.x * w.x + vi1.y * w.y);
        u = sv[c][0][j0 + 3]; w = sv[c][1][j0 + 3];
        val.w = 0.5f * (vi0.x * u.x + vi0.y * u.y + vi1.x * w.x + vi1.y * w.y);
    }

    // ---- broadcast: 14 streaming stores, 4KB contiguous per block per t ----
    // out float4 index: ((b*T + t)*S + 4p + sc_local) * 64 + q
    size_t idx = ((size_t)(b * T_) * S_ + 4 * (size_t)p + sc_local) * 64 + q;
    const size_t t_stride = (size_t)S_ * 64;

#pragma unroll
    for (int t = 0; t < T_; ++t) {
        if (GUARDED) {
            if (idx < n4) __stcs(out4 + idx, val);
        } else {
            __stcs(out4 + idx, val);           // guard-free: pure STG.128 stream
        }
        idx += t_stride;
    }
}

extern "C" void kernel_launch(void* const* d_in, const int* in_sizes, int n_in,
                              void* d_out, int out_size)
{
    // Identify the two big float arrays (3,670,016 elements each) by size;
    // disambiguate real/imag by input ordering (verified in R3).
    const float* big[2] = {nullptr, nullptr};
    int nbig = 0;
    for (int i = 0; i < n_in; ++i) {
        if (in_sizes[i] > 100000 && nbig < 2) big[nbig++] = (const float*)d_in[i];
    }

    const float* y_real;
    const float* y_imag;
    if (in_sizes[0] > 100000) {
        y_real = big[0]; y_imag = big[1];   // insertion order (verified)
    } else {
        y_imag = big[0]; y_real = big[1];   // alphabetical order
    }

    const size_t n4 = (size_t)out_size / 4;

    if (n4 == (size_t)FULL_N4) {
        // Verified full-size output: no per-store bounds checks.
        cov_bcast2_kernel<false><<<B_ * (S2_ / 2), 256>>>(y_real, y_imag,
                                                          (float4*)d_out, n4);
    } else {
        // Unexpected size: guarded variant (cannot fault).
        cov_bcast2_kernel<true><<<B_ * (S2_ / 2), 256>>>(y_real, y_imag,
                                                         (float4*)d_out, n4);
    }
}